// round 1
// baseline (speedup 1.0000x reference)
#include <cuda_runtime.h>
#include <cuda_bf16.h>

// ---------------------------------------------------------------------------
// Attention_64561948394150: seq-first MHA
//   L=2048, B=2, E=256, H=8, D=32, SCALE = 1/sqrt(32)
//   q = query@Wq+bq; k = key@Wk+bk; v = value@Wv+bv
//   attn = softmax(q k^T * scale); out = (attn v) @ Wp + bp
// Round 0: correct fp32 baseline (scalar pipes). Tensor-core rewrite later.
// ---------------------------------------------------------------------------

#define L_SEQ 2048
#define BATCH 2
#define EMB 256
#define NHEAD 8
#define HDIM 32
#define MROWS (L_SEQ * BATCH)          // 4096
#define SCALE 0.17677669529663687f     // 32^-0.5

// Scratch (device globals; no allocation allowed)
__device__ float g_Q[BATCH * NHEAD * L_SEQ * HDIM];   // [b][h][l][d]
__device__ float g_K[BATCH * NHEAD * L_SEQ * HDIM];
__device__ float g_V[BATCH * NHEAD * L_SEQ * HDIM];
__device__ float g_O[MROWS * EMB];                    // [l*B+b][e] row-major

// ---------------------------------------------------------------------------
// Tiled fp32 GEMM: out[M,256] = A[M,256] @ W[256,256] + bias
// headmode=1: scatter output to head-major [b][h][l][d]
// headmode=0: plain row-major write
// BM=BN=64, BK=16, 256 threads, 4x4 micro-tile per thread.
// ---------------------------------------------------------------------------
#define BM 64
#define BN 64
#define BK 16

__global__ __launch_bounds__(256)
void proj_kernel(const float* __restrict__ A, const float* __restrict__ W,
                 const float* __restrict__ bias, float* __restrict__ out,
                 int headmode)
{
    const int K = EMB, N = EMB;
    const int bm = blockIdx.y * BM;
    const int bn = blockIdx.x * BN;

    __shared__ float As[BM][BK + 1];
    __shared__ float Bs[BK][BN + 1];

    const int tid = threadIdx.x;
    const int tx = tid & 15;        // 0..15 -> cols
    const int ty = tid >> 4;        // 0..15 -> rows

    float acc[4][4] = {};

    for (int k0 = 0; k0 < K; k0 += BK) {
        #pragma unroll
        for (int i = tid; i < BM * BK; i += 256) {
            int r = i >> 4, c = i & 15;
            As[r][c] = A[(bm + r) * K + k0 + c];
        }
        #pragma unroll
        for (int i = tid; i < BK * BN; i += 256) {
            int r = i >> 6, c = i & 63;
            Bs[r][c] = W[(k0 + r) * N + bn + c];
        }
        __syncthreads();

        #pragma unroll
        for (int kk = 0; kk < BK; kk++) {
            float a[4], b[4];
            #pragma unroll
            for (int i = 0; i < 4; i++) a[i] = As[ty * 4 + i][kk];
            #pragma unroll
            for (int j = 0; j < 4; j++) b[j] = Bs[kk][tx * 4 + j];
            #pragma unroll
            for (int i = 0; i < 4; i++)
                #pragma unroll
                for (int j = 0; j < 4; j++)
                    acc[i][j] = fmaf(a[i], b[j], acc[i][j]);
        }
        __syncthreads();
    }

    #pragma unroll
    for (int i = 0; i < 4; i++) {
        int row = bm + ty * 4 + i;
        #pragma unroll
        for (int j = 0; j < 4; j++) {
            int col = bn + tx * 4 + j;
            float v = acc[i][j] + bias[col];
            if (headmode) {
                int l = row / BATCH, b = row % BATCH;
                int h = col >> 5, d = col & 31;
                out[(((b * NHEAD + h) * L_SEQ) + l) * HDIM + d] = v;
            } else {
                out[row * N + col] = v;
            }
        }
    }
}

// ---------------------------------------------------------------------------
// Flash-style attention: one thread per query row.
// grid = (L/QT, B*H), block = QT threads. KV tiles of KT=32 in shared.
// ---------------------------------------------------------------------------
#define QT 128
#define KT 32

__global__ __launch_bounds__(QT)
void attn_kernel()
{
    const int bh = blockIdx.y;                   // 0..15  (b*H + h)
    const int q_idx = blockIdx.x * QT + threadIdx.x;

    const float* Qb = g_Q + bh * L_SEQ * HDIM;
    const float* Kb = g_K + bh * L_SEQ * HDIM;
    const float* Vb = g_V + bh * L_SEQ * HDIM;

    __shared__ float Ks[KT][HDIM + 1];
    __shared__ float Vs[KT][HDIM + 1];

    float q[HDIM];
    #pragma unroll
    for (int d = 0; d < HDIM; d++) q[d] = Qb[q_idx * HDIM + d] * SCALE;

    float acc[HDIM] = {};
    float m = -1e30f;
    float s = 0.f;

    for (int k0 = 0; k0 < L_SEQ; k0 += KT) {
        // load K/V tiles (KT*HDIM = 1024 floats each; 8 per thread)
        #pragma unroll
        for (int i = threadIdx.x; i < KT * HDIM; i += QT) {
            int r = i >> 5, c = i & 31;
            Ks[r][c] = Kb[(k0 + r) * HDIM + c];
            Vs[r][c] = Vb[(k0 + r) * HDIM + c];
        }
        __syncthreads();

        float p[KT];
        float mnew = m;
        #pragma unroll
        for (int kk = 0; kk < KT; kk++) {
            float dot = 0.f;
            #pragma unroll
            for (int d = 0; d < HDIM; d++)
                dot = fmaf(q[d], Ks[kk][d], dot);
            p[kk] = dot;
            mnew = fmaxf(mnew, dot);
        }
        float corr = __expf(m - mnew);
        s *= corr;
        #pragma unroll
        for (int d = 0; d < HDIM; d++) acc[d] *= corr;

        #pragma unroll
        for (int kk = 0; kk < KT; kk++) {
            float e = __expf(p[kk] - mnew);
            s += e;
            #pragma unroll
            for (int d = 0; d < HDIM; d++)
                acc[d] = fmaf(e, Vs[kk][d], acc[d]);
        }
        m = mnew;
        __syncthreads();
    }

    // write to g_O in [l*B+b][e] layout, e = h*32 + d
    const int b = bh >> 3;       // bh = b*NHEAD + h
    const int h = bh & 7;
    const float inv_s = 1.0f / s;
    float* orow = g_O + (q_idx * BATCH + b) * EMB + h * HDIM;
    #pragma unroll
    for (int d = 0; d < HDIM; d++) orow[d] = acc[d] * inv_s;
}

// ---------------------------------------------------------------------------
extern "C" void kernel_launch(void* const* d_in, const int* in_sizes, int n_in,
                              void* d_out, int out_size)
{
    const float* query = (const float*)d_in[0];
    const float* key_  = (const float*)d_in[1];
    const float* value = (const float*)d_in[2];
    const float* Wq    = (const float*)d_in[3];
    const float* bq    = (const float*)d_in[4];
    const float* Wk    = (const float*)d_in[5];
    const float* bk    = (const float*)d_in[6];
    const float* Wv    = (const float*)d_in[7];
    const float* bv    = (const float*)d_in[8];
    const float* Wp    = (const float*)d_in[9];
    const float* bp    = (const float*)d_in[10];
    float* out = (float*)d_out;

    float *Qb, *Kb, *Vb, *Ob;
    cudaGetSymbolAddress((void**)&Qb, g_Q);
    cudaGetSymbolAddress((void**)&Kb, g_K);
    cudaGetSymbolAddress((void**)&Vb, g_V);
    cudaGetSymbolAddress((void**)&Ob, g_O);

    dim3 gproj(EMB / BN, MROWS / BM);   // (4, 64)

    proj_kernel<<<gproj, 256>>>(query, Wq, bq, Qb, 1);
    proj_kernel<<<gproj, 256>>>(key_,  Wk, bk, Kb, 1);
    proj_kernel<<<gproj, 256>>>(value, Wv, bv, Vb, 1);

    attn_kernel<<<dim3(L_SEQ / QT, BATCH * NHEAD), QT>>>();

    proj_kernel<<<gproj, 256>>>(Ob, Wp, bp, out, 0);
}

// round 2
// speedup vs baseline: 1.4140x; 1.4140x over previous
#include <cuda_runtime.h>
#include <cuda_bf16.h>
#include <cstdint>

// ---------------------------------------------------------------------------
// Attention_64561948394150: seq-first MHA (L=2048, B=2, E=256, H=8, D=32)
// Round 1: tensor-pipe rewrite.
//   - projections: mma.sync m16n8k8 tf32 with 3xTF32 split (fp32-class accuracy)
//   - attention:   warp-level flash attention, single-pass tf32 mma
// ---------------------------------------------------------------------------

#define L_SEQ 2048
#define BATCH 2
#define EMB 256
#define NHEAD 8
#define HDIM 32
#define MROWS (L_SEQ * BATCH)          // 4096
#define SCALE 0.17677669529663687f     // 32^-0.5

// Scratch (device globals; allocation is forbidden)
__device__ float g_Q[BATCH * NHEAD * L_SEQ * HDIM];   // [b][h][l][d]
__device__ float g_K[BATCH * NHEAD * L_SEQ * HDIM];
__device__ float g_V[BATCH * NHEAD * L_SEQ * HDIM];
__device__ float g_O[MROWS * EMB];                    // [l*B+b][e]

// ---------------------------------------------------------------------------
// helpers
// ---------------------------------------------------------------------------
__device__ __forceinline__ uint32_t f2tf(float x) {
    uint32_t r;
    asm("cvt.rna.tf32.f32 %0, %1;" : "=r"(r) : "f"(x));
    return r;
}

__device__ __forceinline__ void mma8(float* c,
                                     uint32_t a0, uint32_t a1, uint32_t a2, uint32_t a3,
                                     uint32_t b0, uint32_t b1) {
    asm volatile(
        "mma.sync.aligned.m16n8k8.row.col.f32.tf32.tf32.f32 "
        "{%0,%1,%2,%3},{%4,%5,%6,%7},{%8,%9},{%0,%1,%2,%3};"
        : "+f"(c[0]), "+f"(c[1]), "+f"(c[2]), "+f"(c[3])
        : "r"(a0), "r"(a1), "r"(a2), "r"(a3), "r"(b0), "r"(b1));
}

__device__ __forceinline__ void scatter_head(float* out, int row, int col, float v) {
    // row = l*BATCH + b ; col = h*32 + d ; dst layout [b][h][l][d]
    int l = row >> 1, b = row & 1;
    int h = col >> 5, d = col & 31;
    out[(((b * NHEAD + h) * L_SEQ) + l) * HDIM + d] = v;
}

// ---------------------------------------------------------------------------
// Projection GEMM: out[M,256] = A[M,256] @ W[256,256] + bias   (3xTF32)
// block = 128 threads (4 warps). Tile 64x64, K-chunks of 32.
// Each warp computes a 16x64 strip (8 n-tiles of m16n8).
// ---------------------------------------------------------------------------
__global__ __launch_bounds__(128)
void proj_mma(const float* __restrict__ A, const float* __restrict__ W,
              const float* __restrict__ bias, float* __restrict__ out,
              int headmode)
{
    __shared__ float As[64][33];
    __shared__ float Ws[32][65];

    const int tid = threadIdx.x;
    const int warp = tid >> 5, lane = tid & 31;
    const int g = lane >> 2, q = lane & 3;
    const int bm = blockIdx.y * 64, bn = blockIdx.x * 64;

    float acc[8][4] = {};

    for (int k0 = 0; k0 < EMB; k0 += 32) {
        // load A tile 64x32 (512 float4, 4 per thread)
        for (int i = tid; i < 64 * 8; i += 128) {
            int r = i >> 3, c = (i & 7) * 4;
            float4 v = *(const float4*)&A[(size_t)(bm + r) * EMB + k0 + c];
            As[r][c] = v.x; As[r][c + 1] = v.y; As[r][c + 2] = v.z; As[r][c + 3] = v.w;
        }
        // load W tile 32x64
        for (int i = tid; i < 32 * 16; i += 128) {
            int r = i >> 4, c = (i & 15) * 4;
            float4 v = *(const float4*)&W[(size_t)(k0 + r) * EMB + bn + c];
            Ws[r][c] = v.x; Ws[r][c + 1] = v.y; Ws[r][c + 2] = v.z; Ws[r][c + 3] = v.w;
        }
        __syncthreads();

        #pragma unroll
        for (int kc = 0; kc < 4; kc++) {
            float af[4];
            af[0] = As[warp * 16 + g][kc * 8 + q];
            af[1] = As[warp * 16 + g + 8][kc * 8 + q];
            af[2] = As[warp * 16 + g][kc * 8 + q + 4];
            af[3] = As[warp * 16 + g + 8][kc * 8 + q + 4];
            uint32_t ah[4], al[4];
            #pragma unroll
            for (int i = 0; i < 4; i++) {
                ah[i] = f2tf(af[i]);
                al[i] = f2tf(af[i] - __uint_as_float(ah[i]));
            }
            #pragma unroll
            for (int nt = 0; nt < 8; nt++) {
                float bf0 = Ws[kc * 8 + q][nt * 8 + g];
                float bf1 = Ws[kc * 8 + q + 4][nt * 8 + g];
                uint32_t bh0 = f2tf(bf0), bl0 = f2tf(bf0 - __uint_as_float(bh0));
                uint32_t bh1 = f2tf(bf1), bl1 = f2tf(bf1 - __uint_as_float(bh1));
                // 3xTF32: hi*hi + lo*hi + hi*lo
                mma8(acc[nt], ah[0], ah[1], ah[2], ah[3], bh0, bh1);
                mma8(acc[nt], al[0], al[1], al[2], al[3], bh0, bh1);
                mma8(acc[nt], ah[0], ah[1], ah[2], ah[3], bl0, bl1);
            }
        }
        __syncthreads();
    }

    const int r0 = bm + warp * 16 + g;
    #pragma unroll
    for (int nt = 0; nt < 8; nt++) {
        int col = bn + nt * 8 + 2 * q;
        float v00 = acc[nt][0] + bias[col];
        float v01 = acc[nt][1] + bias[col + 1];
        float v10 = acc[nt][2] + bias[col];
        float v11 = acc[nt][3] + bias[col + 1];
        if (headmode) {
            scatter_head(out, r0, col, v00);
            scatter_head(out, r0, col + 1, v01);
            scatter_head(out, r0 + 8, col, v10);
            scatter_head(out, r0 + 8, col + 1, v11);
        } else {
            out[(size_t)r0 * EMB + col] = v00;
            out[(size_t)r0 * EMB + col + 1] = v01;
            out[(size_t)(r0 + 8) * EMB + col] = v10;
            out[(size_t)(r0 + 8) * EMB + col + 1] = v11;
        }
    }
}

// ---------------------------------------------------------------------------
// Flash attention, tf32 mma. block = 128 thr (4 warps), 64 Q-rows per block.
// grid = (L/64, B*H). K/V tiles of 64 in padded shared.
// Per warp: Q strip 16x32 in A-fragments, S (16x64) and O (16x32) in C-frags.
// ---------------------------------------------------------------------------
__global__ __launch_bounds__(128)
void attn_mma()
{
    const int bh = blockIdx.y;
    const int tid = threadIdx.x;
    const int warp = tid >> 5, lane = tid & 31;
    const int g = lane >> 2, q = lane & 3;
    const int qbase = blockIdx.x * 64;

    const float* Qb = g_Q + (size_t)bh * L_SEQ * HDIM;
    const float* Kb = g_K + (size_t)bh * L_SEQ * HDIM;
    const float* Vb = g_V + (size_t)bh * L_SEQ * HDIM;

    __shared__ float Ks[64][33];
    __shared__ float Vs[64][33];

    const int r0 = qbase + warp * 16 + g;   // this thread's rows: r0, r0+8

    // Q fragments (scaled), resident for the whole kernel
    uint32_t aq[4][4];
    #pragma unroll
    for (int kc = 0; kc < 4; kc++) {
        aq[kc][0] = f2tf(Qb[(size_t)r0 * HDIM + kc * 8 + q] * SCALE);
        aq[kc][1] = f2tf(Qb[(size_t)(r0 + 8) * HDIM + kc * 8 + q] * SCALE);
        aq[kc][2] = f2tf(Qb[(size_t)r0 * HDIM + kc * 8 + q + 4] * SCALE);
        aq[kc][3] = f2tf(Qb[(size_t)(r0 + 8) * HDIM + kc * 8 + q + 4] * SCALE);
    }

    float o[4][4] = {};
    float m0 = -1e30f, m1 = -1e30f, l0 = 0.f, l1 = 0.f;

    for (int k0 = 0; k0 < L_SEQ; k0 += 64) {
        // load K/V tiles (64x32 each; 4 float4 per thread per tensor)
        for (int i = tid; i < 512; i += 128) {
            int rr = i >> 3, cc = (i & 7) * 4;
            float4 kv = *(const float4*)&Kb[(size_t)(k0 + rr) * HDIM + cc];
            Ks[rr][cc] = kv.x; Ks[rr][cc + 1] = kv.y; Ks[rr][cc + 2] = kv.z; Ks[rr][cc + 3] = kv.w;
            float4 vv = *(const float4*)&Vb[(size_t)(k0 + rr) * HDIM + cc];
            Vs[rr][cc] = vv.x; Vs[rr][cc + 1] = vv.y; Vs[rr][cc + 2] = vv.z; Vs[rr][cc + 3] = vv.w;
        }
        __syncthreads();

        // S = Q K^T  (16x64 per warp, 8 n-tiles)
        float s[8][4] = {};
        #pragma unroll
        for (int kc = 0; kc < 4; kc++) {
            #pragma unroll
            for (int nt = 0; nt < 8; nt++) {
                uint32_t b0 = f2tf(Ks[nt * 8 + g][kc * 8 + q]);
                uint32_t b1 = f2tf(Ks[nt * 8 + g][kc * 8 + q + 4]);
                mma8(s[nt], aq[kc][0], aq[kc][1], aq[kc][2], aq[kc][3], b0, b1);
            }
        }

        // online softmax: row maxima via quad shuffles
        float mx0 = -1e30f, mx1 = -1e30f;
        #pragma unroll
        for (int nt = 0; nt < 8; nt++) {
            mx0 = fmaxf(mx0, fmaxf(s[nt][0], s[nt][1]));
            mx1 = fmaxf(mx1, fmaxf(s[nt][2], s[nt][3]));
        }
        mx0 = fmaxf(mx0, __shfl_xor_sync(0xffffffffu, mx0, 1));
        mx0 = fmaxf(mx0, __shfl_xor_sync(0xffffffffu, mx0, 2));
        mx1 = fmaxf(mx1, __shfl_xor_sync(0xffffffffu, mx1, 1));
        mx1 = fmaxf(mx1, __shfl_xor_sync(0xffffffffu, mx1, 2));
        float nm0 = fmaxf(m0, mx0), nm1 = fmaxf(m1, mx1);
        float cr0 = __expf(m0 - nm0), cr1 = __expf(m1 - nm1);
        m0 = nm0; m1 = nm1;

        float sum0 = 0.f, sum1 = 0.f;
        #pragma unroll
        for (int nt = 0; nt < 8; nt++) {
            s[nt][0] = __expf(s[nt][0] - nm0);
            s[nt][1] = __expf(s[nt][1] - nm0);
            s[nt][2] = __expf(s[nt][2] - nm1);
            s[nt][3] = __expf(s[nt][3] - nm1);
            sum0 += s[nt][0] + s[nt][1];
            sum1 += s[nt][2] + s[nt][3];
        }
        sum0 += __shfl_xor_sync(0xffffffffu, sum0, 1);
        sum0 += __shfl_xor_sync(0xffffffffu, sum0, 2);
        sum1 += __shfl_xor_sync(0xffffffffu, sum1, 1);
        sum1 += __shfl_xor_sync(0xffffffffu, sum1, 2);
        l0 = l0 * cr0 + sum0;
        l1 = l1 * cr1 + sum1;

        #pragma unroll
        for (int vt = 0; vt < 4; vt++) {
            o[vt][0] *= cr0; o[vt][1] *= cr0;
            o[vt][2] *= cr1; o[vt][3] *= cr1;
        }

        // O += P V : convert each 16x8 P tile from C-layout to A-layout via shuffles
        #pragma unroll
        for (int kc = 0; kc < 8; kc++) {
            int src = (lane & ~3) | (q >> 1);
            float t0 = __shfl_sync(0xffffffffu, s[kc][0], src);
            float t1 = __shfl_sync(0xffffffffu, s[kc][1], src);
            float t2 = __shfl_sync(0xffffffffu, s[kc][2], src);
            float t3 = __shfl_sync(0xffffffffu, s[kc][3], src);
            float u0 = __shfl_sync(0xffffffffu, s[kc][0], src + 2);
            float u1 = __shfl_sync(0xffffffffu, s[kc][1], src + 2);
            float u2 = __shfl_sync(0xffffffffu, s[kc][2], src + 2);
            float u3 = __shfl_sync(0xffffffffu, s[kc][3], src + 2);
            bool odd = (q & 1);
            uint32_t A0 = f2tf(odd ? t1 : t0);
            uint32_t A1 = f2tf(odd ? t3 : t2);
            uint32_t A2 = f2tf(odd ? u1 : u0);
            uint32_t A3 = f2tf(odd ? u3 : u2);
            #pragma unroll
            for (int vt = 0; vt < 4; vt++) {
                uint32_t b0 = f2tf(Vs[kc * 8 + q][vt * 8 + g]);
                uint32_t b1 = f2tf(Vs[kc * 8 + q + 4][vt * 8 + g]);
                mma8(o[vt], A0, A1, A2, A3, b0, b1);
            }
        }
        __syncthreads();
    }

    // epilogue: normalize and write to g_O [l*B+b][h*32+d]
    const int b = bh >> 3, h = bh & 7;
    float iv0 = 1.f / l0, iv1 = 1.f / l1;
    #pragma unroll
    for (int vt = 0; vt < 4; vt++) {
        int col = h * HDIM + vt * 8 + 2 * q;
        g_O[(size_t)(r0 * BATCH + b) * EMB + col]       = o[vt][0] * iv0;
        g_O[(size_t)(r0 * BATCH + b) * EMB + col + 1]   = o[vt][1] * iv0;
        g_O[(size_t)((r0 + 8) * BATCH + b) * EMB + col]     = o[vt][2] * iv1;
        g_O[(size_t)((r0 + 8) * BATCH + b) * EMB + col + 1] = o[vt][3] * iv1;
    }
}

// ---------------------------------------------------------------------------
extern "C" void kernel_launch(void* const* d_in, const int* in_sizes, int n_in,
                              void* d_out, int out_size)
{
    const float* query = (const float*)d_in[0];
    const float* key_  = (const float*)d_in[1];
    const float* value = (const float*)d_in[2];
    const float* Wq    = (const float*)d_in[3];
    const float* bq    = (const float*)d_in[4];
    const float* Wk    = (const float*)d_in[5];
    const float* bk    = (const float*)d_in[6];
    const float* Wv    = (const float*)d_in[7];
    const float* bv    = (const float*)d_in[8];
    const float* Wp    = (const float*)d_in[9];
    const float* bp    = (const float*)d_in[10];
    float* out = (float*)d_out;

    float *Qb, *Kb, *Vb, *Ob;
    cudaGetSymbolAddress((void**)&Qb, g_Q);
    cudaGetSymbolAddress((void**)&Kb, g_K);
    cudaGetSymbolAddress((void**)&Vb, g_V);
    cudaGetSymbolAddress((void**)&Ob, g_O);

    dim3 gproj(EMB / 64, MROWS / 64);   // (4, 64)

    proj_mma<<<gproj, 128>>>(query, Wq, bq, Qb, 1);
    proj_mma<<<gproj, 128>>>(key_,  Wk, bk, Kb, 1);
    proj_mma<<<gproj, 128>>>(value, Wv, bv, Vb, 1);

    attn_mma<<<dim3(L_SEQ / 64, BATCH * NHEAD), 128>>>();

    proj_mma<<<gproj, 128>>>(Ob, Wp, bp, out, 0);
}

// round 3
// speedup vs baseline: 1.6655x; 1.1779x over previous
#include <cuda_runtime.h>
#include <cuda_bf16.h>
#include <cstdint>

// ---------------------------------------------------------------------------
// Attention_64561948394150: seq-first MHA (L=2048, B=2, E=256, H=8, D=32)
// Round 2: MIO-traffic removal.
//  - K stored [l][dperm] tf32, V stored [d][lperm] tf32 (perms make every
//    mma B-fragment an LDS.128 and make S C-frags == PV A-frags, no shuffles)
//  - Q pre-scaled at projection
//  - cp.async double buffering in attention
//  - fused QKV projection, hi/lo tf32 split done once at tile load
// ---------------------------------------------------------------------------

#define L_SEQ 2048
#define BATCH 2
#define EMB 256
#define NHEAD 8
#define HDIM 32
#define MROWS (L_SEQ * BATCH)
#define SCALE 0.17677669529663687f

#define KS_STRIDE 36
#define VT_STRIDE 72

__device__ float g_Q[BATCH * NHEAD * L_SEQ * HDIM];   // [b][h][l][d]   (f32, pre-scaled)
__device__ float g_K[BATCH * NHEAD * L_SEQ * HDIM];   // [b][h][l][dperm] (tf32 bits)
__device__ float g_V[BATCH * NHEAD * HDIM * L_SEQ];   // [b][h][d][lperm] (tf32 bits)
__device__ float g_O[MROWS * EMB];                    // [l*B+b][e]

// ---------------------------------------------------------------------------
__device__ __forceinline__ uint32_t f2tf(float x) {
    uint32_t r;
    asm("cvt.rna.tf32.f32 %0, %1;" : "=r"(r) : "f"(x));
    return r;
}
__device__ __forceinline__ uint32_t fu(float x) { return __float_as_uint(x); }

__device__ __forceinline__ void mma8(float* c,
                                     uint32_t a0, uint32_t a1, uint32_t a2, uint32_t a3,
                                     uint32_t b0, uint32_t b1) {
    asm volatile(
        "mma.sync.aligned.m16n8k8.row.col.f32.tf32.tf32.f32 "
        "{%0,%1,%2,%3},{%4,%5,%6,%7},{%8,%9},{%0,%1,%2,%3};"
        : "+f"(c[0]), "+f"(c[1]), "+f"(c[2]), "+f"(c[3])
        : "r"(a0), "r"(a1), "r"(a2), "r"(a3), "r"(b0), "r"(b1));
}

// d within head (0..31) -> permuted column so B-fragments are contiguous
__device__ __forceinline__ int dperm(int d) {
    return (d & 3) * 8 + ((d >> 3) << 1) + ((d >> 2) & 1);
}
// kv index l -> permuted column in V^T storage (within 64-blocks)
__device__ __forceinline__ int vperm(int l) {
    int j = l & 63, r = j & 7, b8 = j >> 3;
    int p8 = (r & 1) ? ((r >> 1) + 4) : (r >> 1);
    int p = b8 * 8 + p8;
    return (l & ~63) + (p & 3) * 16 + ((p >> 3) << 1) + ((p >> 2) & 1);
}

#define CP_ASYNC16(dst, src) \
    asm volatile("cp.async.cg.shared.global [%0], [%1], 16;" :: "r"(dst), "l"(src))
#define CP_COMMIT() asm volatile("cp.async.commit_group;")
#define CP_WAIT0()  asm volatile("cp.async.wait_group 0;")

// ---------------------------------------------------------------------------
// Projection core: out = A[4096,256] @ W[256,256] + bias, 3xTF32.
// hi/lo split performed ONCE at tile load into shared; fragments read as
// LDS.128 via permuted column layouts. mode: 0=plain f32, 1=Q, 2=K, 3=V.
// ---------------------------------------------------------------------------
__device__ __forceinline__ void store_proj(float* out, int mode, int row, int col, float val)
{
    if (mode == 0) {
        out[(size_t)row * EMB + col] = val;
    } else {
        int l = row >> 1, b = row & 1;
        int h = col >> 5, d = col & 31;
        if (mode == 1) {
            out[(((size_t)(b * NHEAD + h) * L_SEQ) + l) * HDIM + d] = val * SCALE;
        } else if (mode == 2) {
            out[(((size_t)(b * NHEAD + h) * L_SEQ) + l) * HDIM + dperm(d)] =
                __uint_as_float(f2tf(val));
        } else {
            out[((size_t)(b * NHEAD + h) * HDIM + d) * L_SEQ + vperm(l)] =
                __uint_as_float(f2tf(val));
        }
    }
}

__device__ __forceinline__ void proj_body(const float* __restrict__ A,
                                          const float* __restrict__ W,
                                          const float* __restrict__ bias,
                                          float* __restrict__ out, int mode)
{
    __shared__ float Ah[64 * KS_STRIDE], Al[64 * KS_STRIDE];
    __shared__ float Wh[64 * KS_STRIDE], Wl[64 * KS_STRIDE];

    const int tid = threadIdx.x;
    const int warp = tid >> 5, lane = tid & 31;
    const int g = lane >> 2, q = lane & 3;
    const int bm = blockIdx.y * 64, bn = blockIdx.x * 64;

    float acc[8][4] = {};

    for (int k0 = 0; k0 < EMB; k0 += 32) {
        // A tile 64x32: split hi/lo, permuted columns
        #pragma unroll
        for (int j = 0; j < 4; j++) {
            int i = tid + 128 * j;
            int row = i >> 3, c = (i & 7) * 4;
            float4 v = *(const float4*)&A[(size_t)(bm + row) * EMB + k0 + c];
            float xs[4] = {v.x, v.y, v.z, v.w};
            #pragma unroll
            for (int e = 0; e < 4; e++) {
                int kl = c + e;
                int kp = (kl & 3) * 8 + ((kl >> 3) << 1) + ((kl >> 2) & 1);
                uint32_t hi = f2tf(xs[e]);
                Ah[row * KS_STRIDE + kp] = __uint_as_float(hi);
                Al[row * KS_STRIDE + kp] =
                    __uint_as_float(f2tf(xs[e] - __uint_as_float(hi)));
            }
        }
        // W tile 32x64, stored transposed [n][kperm]
        #pragma unroll
        for (int j = 0; j < 4; j++) {
            int i = tid + 128 * j;
            int kl = i >> 4, c = (i & 15) * 4;
            float4 v = *(const float4*)&W[(size_t)(k0 + kl) * EMB + bn + c];
            int kp = (kl & 3) * 8 + ((kl >> 3) << 1) + ((kl >> 2) & 1);
            float xs[4] = {v.x, v.y, v.z, v.w};
            #pragma unroll
            for (int e = 0; e < 4; e++) {
                int n = c + e;
                uint32_t hi = f2tf(xs[e]);
                Wh[n * KS_STRIDE + kp] = __uint_as_float(hi);
                Wl[n * KS_STRIDE + kp] =
                    __uint_as_float(f2tf(xs[e] - __uint_as_float(hi)));
            }
        }
        __syncthreads();

        // A fragments: rows g, g+8 of this warp's strip; cols q*8..q*8+7
        int ra0 = (warp * 16 + g) * KS_STRIDE + q * 8;
        int ra1 = ra0 + 8 * KS_STRIDE;
        float4 h00 = *(const float4*)&Ah[ra0], h01 = *(const float4*)&Ah[ra0 + 4];
        float4 h10 = *(const float4*)&Ah[ra1], h11 = *(const float4*)&Ah[ra1 + 4];
        float4 l00 = *(const float4*)&Al[ra0], l01 = *(const float4*)&Al[ra0 + 4];
        float4 l10 = *(const float4*)&Al[ra1], l11 = *(const float4*)&Al[ra1 + 4];
        float ah0[8] = {h00.x, h00.y, h00.z, h00.w, h01.x, h01.y, h01.z, h01.w};
        float ah1[8] = {h10.x, h10.y, h10.z, h10.w, h11.x, h11.y, h11.z, h11.w};
        float al0[8] = {l00.x, l00.y, l00.z, l00.w, l01.x, l01.y, l01.z, l01.w};
        float al1[8] = {l10.x, l10.y, l10.z, l10.w, l11.x, l11.y, l11.z, l11.w};

        #pragma unroll
        for (int nt = 0; nt < 8; nt++) {
            int rw = (nt * 8 + g) * KS_STRIDE + q * 8;
            float4 w0 = *(const float4*)&Wh[rw], w1 = *(const float4*)&Wh[rw + 4];
            float4 x0 = *(const float4*)&Wl[rw], x1 = *(const float4*)&Wl[rw + 4];
            float wh[8] = {w0.x, w0.y, w0.z, w0.w, w1.x, w1.y, w1.z, w1.w};
            float wl[8] = {x0.x, x0.y, x0.z, x0.w, x1.x, x1.y, x1.z, x1.w};
            #pragma unroll
            for (int kc = 0; kc < 4; kc++) {
                uint32_t A0 = fu(ah0[kc * 2]),     A1 = fu(ah1[kc * 2]);
                uint32_t A2 = fu(ah0[kc * 2 + 1]), A3 = fu(ah1[kc * 2 + 1]);
                uint32_t L0 = fu(al0[kc * 2]),     L1 = fu(al1[kc * 2]);
                uint32_t L2 = fu(al0[kc * 2 + 1]), L3 = fu(al1[kc * 2 + 1]);
                uint32_t B0 = fu(wh[kc * 2]), B1 = fu(wh[kc * 2 + 1]);
                uint32_t C0 = fu(wl[kc * 2]), C1 = fu(wl[kc * 2 + 1]);
                mma8(acc[nt], A0, A1, A2, A3, B0, B1);   // hi*hi
                mma8(acc[nt], L0, L1, L2, L3, B0, B1);   // lo*hi
                mma8(acc[nt], A0, A1, A2, A3, C0, C1);   // hi*lo
            }
        }
        __syncthreads();
    }

    const int r0 = bm + warp * 16 + g;
    #pragma unroll
    for (int nt = 0; nt < 8; nt++) {
        int col = bn + nt * 8 + 2 * q;
        store_proj(out, mode, r0,     col,     acc[nt][0] + bias[col]);
        store_proj(out, mode, r0,     col + 1, acc[nt][1] + bias[col + 1]);
        store_proj(out, mode, r0 + 8, col,     acc[nt][2] + bias[col]);
        store_proj(out, mode, r0 + 8, col + 1, acc[nt][3] + bias[col + 1]);
    }
}

__global__ __launch_bounds__(128)
void qkv_proj(const float* __restrict__ q_in, const float* __restrict__ k_in,
              const float* __restrict__ v_in,
              const float* __restrict__ Wq, const float* __restrict__ bq,
              const float* __restrict__ Wk, const float* __restrict__ bk,
              const float* __restrict__ Wv, const float* __restrict__ bv,
              float* __restrict__ Qo, float* __restrict__ Ko, float* __restrict__ Vo)
{
    int z = blockIdx.z;
    const float* A = (z == 0) ? q_in : (z == 1) ? k_in : v_in;
    const float* W = (z == 0) ? Wq : (z == 1) ? Wk : Wv;
    const float* b = (z == 0) ? bq : (z == 1) ? bk : bv;
    float* out     = (z == 0) ? Qo : (z == 1) ? Ko : Vo;
    proj_body(A, W, b, out, z + 1);
}

__global__ __launch_bounds__(128)
void final_proj(const float* __restrict__ A, const float* __restrict__ W,
                const float* __restrict__ bias, float* __restrict__ out)
{
    proj_body(A, W, bias, out, 0);
}

// ---------------------------------------------------------------------------
// Flash attention. block=128 thr (4 warps), 64 Q-rows/block, grid=(32, 16).
// K tiles [64][32] (dperm cols), V^T tiles [32][64+gap] (lperm cols), both
// pre-converted tf32. cp.async double buffered.
// ---------------------------------------------------------------------------
__global__ __launch_bounds__(128)
void attn_mma()
{
    __shared__ float Ks[2][64 * KS_STRIDE];
    __shared__ float VT[2][32 * VT_STRIDE];

    const int bh = blockIdx.y;
    const int tid = threadIdx.x;
    const int warp = tid >> 5, lane = tid & 31;
    const int g = lane >> 2, q = lane & 3;
    const int qbase = blockIdx.x * 64;

    const float* Qb = g_Q + (size_t)bh * L_SEQ * HDIM;
    const float* Kb = g_K + (size_t)bh * L_SEQ * HDIM;
    const float* Vb = g_V + (size_t)bh * HDIM * L_SEQ;

    uint32_t ks_s[2], vt_s[2];
    ks_s[0] = (uint32_t)__cvta_generic_to_shared(&Ks[0][0]);
    ks_s[1] = (uint32_t)__cvta_generic_to_shared(&Ks[1][0]);
    vt_s[0] = (uint32_t)__cvta_generic_to_shared(&VT[0][0]);
    vt_s[1] = (uint32_t)__cvta_generic_to_shared(&VT[1][0]);

    // issue cp.async for tile t into buffer buf
    auto issue_tile = [&](int t, int buf) {
        const float* Kt = Kb + (size_t)t * 64 * HDIM;
        const float* Vt = Vb + (size_t)t * 64;
        #pragma unroll
        for (int j = 0; j < 4; j++) {
            int i = tid + 128 * j;
            int row = i >> 3, c = (i & 7) * 4;
            CP_ASYNC16(ks_s[buf] + (row * KS_STRIDE + c) * 4, Kt + row * HDIM + c);
        }
        #pragma unroll
        for (int j = 0; j < 4; j++) {
            int i = tid + 128 * j;
            int row = i >> 4, c = (i & 15) * 4;
            int cc = c + ((c >= 32) ? 4 : 0);
            CP_ASYNC16(vt_s[buf] + (row * VT_STRIDE + cc) * 4, Vt + (size_t)row * L_SEQ + c);
        }
        CP_COMMIT();
    };

    issue_tile(0, 0);

    const int r0 = qbase + warp * 16 + g;

    // Q fragments (already scaled), resident all kernel
    uint32_t aq[4][4];
    #pragma unroll
    for (int kc = 0; kc < 4; kc++) {
        aq[kc][0] = f2tf(Qb[(size_t)r0 * HDIM + kc * 8 + q]);
        aq[kc][1] = f2tf(Qb[(size_t)(r0 + 8) * HDIM + kc * 8 + q]);
        aq[kc][2] = f2tf(Qb[(size_t)r0 * HDIM + kc * 8 + q + 4]);
        aq[kc][3] = f2tf(Qb[(size_t)(r0 + 8) * HDIM + kc * 8 + q + 4]);
    }

    float o[4][4] = {};
    float m0 = -1e30f, m1 = -1e30f, l0 = 0.f, l1 = 0.f;

    const int vt_q_base = q * 16 + ((q >= 2) ? 4 : 0);

    for (int t = 0; t < L_SEQ / 64; t++) {
        CP_WAIT0();
        __syncthreads();
        if (t + 1 < L_SEQ / 64) issue_tile(t + 1, (t + 1) & 1);
        const int buf = t & 1;

        // ---- S = Q K^T : per nt tile, 2 LDS.128 give all 4 kc B-pairs ----
        float s[8][4] = {};
        #pragma unroll
        for (int nt = 0; nt < 8; nt++) {
            const float* kr = &Ks[buf][(nt * 8 + g) * KS_STRIDE + q * 8];
            float4 b01 = *(const float4*)kr;
            float4 b23 = *(const float4*)(kr + 4);
            mma8(s[nt], aq[0][0], aq[0][1], aq[0][2], aq[0][3], fu(b01.x), fu(b01.y));
            mma8(s[nt], aq[1][0], aq[1][1], aq[1][2], aq[1][3], fu(b01.z), fu(b01.w));
            mma8(s[nt], aq[2][0], aq[2][1], aq[2][2], aq[2][3], fu(b23.x), fu(b23.y));
            mma8(s[nt], aq[3][0], aq[3][1], aq[3][2], aq[3][3], fu(b23.z), fu(b23.w));
        }

        // ---- online softmax ----
        float mx0 = -1e30f, mx1 = -1e30f;
        #pragma unroll
        for (int nt = 0; nt < 8; nt++) {
            mx0 = fmaxf(mx0, fmaxf(s[nt][0], s[nt][1]));
            mx1 = fmaxf(mx1, fmaxf(s[nt][2], s[nt][3]));
        }
        mx0 = fmaxf(mx0, __shfl_xor_sync(0xffffffffu, mx0, 1));
        mx0 = fmaxf(mx0, __shfl_xor_sync(0xffffffffu, mx0, 2));
        mx1 = fmaxf(mx1, __shfl_xor_sync(0xffffffffu, mx1, 1));
        mx1 = fmaxf(mx1, __shfl_xor_sync(0xffffffffu, mx1, 2));
        float nm0 = fmaxf(m0, mx0), nm1 = fmaxf(m1, mx1);
        float cr0 = __expf(m0 - nm0), cr1 = __expf(m1 - nm1);
        m0 = nm0; m1 = nm1;

        float sum0 = 0.f, sum1 = 0.f;
        #pragma unroll
        for (int nt = 0; nt < 8; nt++) {
            s[nt][0] = __expf(s[nt][0] - nm0);
            s[nt][1] = __expf(s[nt][1] - nm0);
            s[nt][2] = __expf(s[nt][2] - nm1);
            s[nt][3] = __expf(s[nt][3] - nm1);
            sum0 += s[nt][0] + s[nt][1];
            sum1 += s[nt][2] + s[nt][3];
        }
        sum0 += __shfl_xor_sync(0xffffffffu, sum0, 1);
        sum0 += __shfl_xor_sync(0xffffffffu, sum0, 2);
        sum1 += __shfl_xor_sync(0xffffffffu, sum1, 1);
        sum1 += __shfl_xor_sync(0xffffffffu, sum1, 2);
        l0 = l0 * cr0 + sum0;
        l1 = l1 * cr1 + sum1;

        #pragma unroll
        for (int vt = 0; vt < 4; vt++) {
            o[vt][0] *= cr0; o[vt][1] *= cr0;
            o[vt][2] *= cr1; o[vt][3] *= cr1;
        }

        // ---- P A-fragments: pure register renaming (V's kv-perm), + cvt ----
        uint32_t pa[8][4];
        #pragma unroll
        for (int kc = 0; kc < 8; kc++) {
            pa[kc][0] = f2tf(s[kc][0]);
            pa[kc][1] = f2tf(s[kc][2]);
            pa[kc][2] = f2tf(s[kc][1]);
            pa[kc][3] = f2tf(s[kc][3]);
        }

        // ---- O += P V : per vt, 4 LDS.128 give all 8 kc B-pairs ----
        #pragma unroll
        for (int vt = 0; vt < 4; vt++) {
            const float* vr = &VT[buf][(vt * 8 + g) * VT_STRIDE + vt_q_base];
            float4 v0 = *(const float4*)vr;
            float4 v1 = *(const float4*)(vr + 4);
            float4 v2 = *(const float4*)(vr + 8);
            float4 v3 = *(const float4*)(vr + 12);
            mma8(o[vt], pa[0][0], pa[0][1], pa[0][2], pa[0][3], fu(v0.x), fu(v0.y));
            mma8(o[vt], pa[1][0], pa[1][1], pa[1][2], pa[1][3], fu(v0.z), fu(v0.w));
            mma8(o[vt], pa[2][0], pa[2][1], pa[2][2], pa[2][3], fu(v1.x), fu(v1.y));
            mma8(o[vt], pa[3][0], pa[3][1], pa[3][2], pa[3][3], fu(v1.z), fu(v1.w));
            mma8(o[vt], pa[4][0], pa[4][1], pa[4][2], pa[4][3], fu(v2.x), fu(v2.y));
            mma8(o[vt], pa[5][0], pa[5][1], pa[5][2], pa[5][3], fu(v2.z), fu(v2.w));
            mma8(o[vt], pa[6][0], pa[6][1], pa[6][2], pa[6][3], fu(v3.x), fu(v3.y));
            mma8(o[vt], pa[7][0], pa[7][1], pa[7][2], pa[7][3], fu(v3.z), fu(v3.w));
        }
    }

    // epilogue
    const int b = bh >> 3, h = bh & 7;
    float iv0 = 1.f / l0, iv1 = 1.f / l1;
    #pragma unroll
    for (int vt = 0; vt < 4; vt++) {
        int col = h * HDIM + vt * 8 + 2 * q;
        g_O[(size_t)(r0 * BATCH + b) * EMB + col]           = o[vt][0] * iv0;
        g_O[(size_t)(r0 * BATCH + b) * EMB + col + 1]       = o[vt][1] * iv0;
        g_O[(size_t)((r0 + 8) * BATCH + b) * EMB + col]     = o[vt][2] * iv1;
        g_O[(size_t)((r0 + 8) * BATCH + b) * EMB + col + 1] = o[vt][3] * iv1;
    }
}

// ---------------------------------------------------------------------------
extern "C" void kernel_launch(void* const* d_in, const int* in_sizes, int n_in,
                              void* d_out, int out_size)
{
    const float* query = (const float*)d_in[0];
    const float* key_  = (const float*)d_in[1];
    const float* value = (const float*)d_in[2];
    const float* Wq    = (const float*)d_in[3];
    const float* bq    = (const float*)d_in[4];
    const float* Wk    = (const float*)d_in[5];
    const float* bk    = (const float*)d_in[6];
    const float* Wv    = (const float*)d_in[7];
    const float* bv    = (const float*)d_in[8];
    const float* Wp    = (const float*)d_in[9];
    const float* bp    = (const float*)d_in[10];
    float* out = (float*)d_out;

    float *Qb, *Kb, *Vb, *Ob;
    cudaGetSymbolAddress((void**)&Qb, g_Q);
    cudaGetSymbolAddress((void**)&Kb, g_K);
    cudaGetSymbolAddress((void**)&Vb, g_V);
    cudaGetSymbolAddress((void**)&Ob, g_O);

    qkv_proj<<<dim3(EMB / 64, MROWS / 64, 3), 128>>>(
        query, key_, value, Wq, bq, Wk, bk, Wv, bv, Qb, Kb, Vb);

    attn_mma<<<dim3(L_SEQ / 64, BATCH * NHEAD), 128>>>();

    final_proj<<<dim3(EMB / 64, MROWS / 64), 128>>>(Ob, Wp, bp, out);
}

// round 4
// speedup vs baseline: 2.8221x; 1.6945x over previous
#include <cuda_runtime.h>
#include <cuda_bf16.h>
#include <cstdint>

// ---------------------------------------------------------------------------
// Attention_64561948394150: seq-first MHA (L=2048, B=2, E=256, H=8, D=32)
// Round 3: pre-split 3xTF32 projections (no cvt/STS in GEMM), cp.async
// double-buffered; attention epilogue emits hi/lo permuted directly.
// ---------------------------------------------------------------------------

#define L_SEQ 2048
#define BATCH 2
#define EMB 256
#define NHEAD 8
#define HDIM 32
#define MROWS 4096
#define SCALE 0.17677669529663687f
#define KS_STRIDE 36
#define VT_STRIDE 72

// attention operand scratch
__device__ float g_Q[BATCH * NHEAD * L_SEQ * HDIM];   // [b][h][l][d] f32 pre-scaled
__device__ float g_K[BATCH * NHEAD * L_SEQ * HDIM];   // [b][h][l][dperm] tf32 bits
__device__ float g_V[BATCH * NHEAD * HDIM * L_SEQ];   // [b][h][d][lperm] tf32 bits
// pre-split activations / weights / attn-output (fragment-permuted layouts)
__device__ float gAh[3][MROWS * EMB], gAl[3][MROWS * EMB];
__device__ float gWh[4][EMB * EMB],  gWl[4][EMB * EMB];   // transposed [n][kperm]
__device__ float gOh[MROWS * EMB],   gOl[MROWS * EMB];

// ---------------------------------------------------------------------------
__device__ __forceinline__ uint32_t f2tf(float x) {
    uint32_t r;
    asm("cvt.rna.tf32.f32 %0, %1;" : "=r"(r) : "f"(x));
    return r;
}
__device__ __forceinline__ uint32_t fu(float x) { return __float_as_uint(x); }

__device__ __forceinline__ void mma8(float* c,
                                     uint32_t a0, uint32_t a1, uint32_t a2, uint32_t a3,
                                     uint32_t b0, uint32_t b1) {
    asm volatile(
        "mma.sync.aligned.m16n8k8.row.col.f32.tf32.tf32.f32 "
        "{%0,%1,%2,%3},{%4,%5,%6,%7},{%8,%9},{%0,%1,%2,%3};"
        : "+f"(c[0]), "+f"(c[1]), "+f"(c[2]), "+f"(c[3])
        : "r"(a0), "r"(a1), "r"(a2), "r"(a3), "r"(b0), "r"(b1));
}

// k within a 32-chunk -> permuted column (fragment LDS.128 contiguity)
__device__ __forceinline__ int kperm32(int kl) {
    return (kl & 3) * 8 + ((kl >> 3) << 1) + ((kl >> 2) & 1);
}
// kv index l -> permuted column in V^T storage (within 64-blocks)
__device__ __forceinline__ int vperm(int l) {
    int j = l & 63, r = j & 7, b8 = j >> 3;
    int p8 = (r & 1) ? ((r >> 1) + 4) : (r >> 1);
    int p = b8 * 8 + p8;
    return (l & ~63) + (p & 3) * 16 + ((p >> 3) << 1) + ((p >> 2) & 1);
}

#define CP_ASYNC16(dst, src) \
    asm volatile("cp.async.cg.shared.global [%0], [%1], 16;" :: "r"(dst), "l"(src))
#define CP_COMMIT() asm volatile("cp.async.commit_group;")
#define CP_WAIT0()  asm volatile("cp.async.wait_group 0;")

// ---------------------------------------------------------------------------
// setup: split activations (query/key/value) into hi/lo permuted layout
// ---------------------------------------------------------------------------
__global__ __launch_bounds__(256)
void split_act(const float* __restrict__ q_in, const float* __restrict__ k_in,
               const float* __restrict__ v_in)
{
    int i = blockIdx.x * 256 + threadIdx.x;          // 0 .. 3*4096*64-1
    int z = i >> 18;                                  // 262144 float4 per input
    int r = i & 262143;
    int row = r >> 6;
    int kk = (r & 63) * 4;
    const float* in = (z == 0) ? q_in : (z == 1) ? k_in : v_in;
    float4 v = *(const float4*)&in[(size_t)row * EMB + kk];
    float xs[4] = {v.x, v.y, v.z, v.w};
    int base = row * EMB + (kk >> 5) * 32;
    float* oh = gAh[z];
    float* ol = gAl[z];
    #pragma unroll
    for (int e = 0; e < 4; e++) {
        int kp = kperm32((kk + e) & 31);
        uint32_t hi = f2tf(xs[e]);
        oh[base + kp] = __uint_as_float(hi);
        ol[base + kp] = __uint_as_float(f2tf(xs[e] - __uint_as_float(hi)));
    }
}

// setup: split + transpose + permute the 4 weight matrices
__global__ __launch_bounds__(256)
void split_w(const float* __restrict__ Wq, const float* __restrict__ Wk,
             const float* __restrict__ Wv, const float* __restrict__ Wp)
{
    int i = blockIdx.x * 256 + threadIdx.x;          // 0 .. 4*256*64-1
    int w = i >> 14;                                  // 16384 float4 per weight
    int r = i & 16383;
    int kk = r >> 6;
    int n4 = (r & 63) * 4;
    const float* W = (w == 0) ? Wq : (w == 1) ? Wk : (w == 2) ? Wv : Wp;
    float4 v = *(const float4*)&W[(size_t)kk * EMB + n4];
    float xs[4] = {v.x, v.y, v.z, v.w};
    int kcol = (kk >> 5) * 32 + kperm32(kk & 31);
    #pragma unroll
    for (int e = 0; e < 4; e++) {
        uint32_t hi = f2tf(xs[e]);
        gWh[w][(size_t)(n4 + e) * EMB + kcol] = __uint_as_float(hi);
        gWl[w][(size_t)(n4 + e) * EMB + kcol] =
            __uint_as_float(f2tf(xs[e] - __uint_as_float(hi)));
    }
}

// ---------------------------------------------------------------------------
// epilogue store: mode 0 = plain f32, 1 = Q (scaled f32), 2 = K tf32 perm,
// 3 = V tf32 perm-transposed
// ---------------------------------------------------------------------------
__device__ __forceinline__ void store_proj(float* out, int mode, int row, int col, float val)
{
    if (mode == 0) {
        out[(size_t)row * EMB + col] = val;
    } else {
        int l = row >> 1, b = row & 1;
        int h = col >> 5, d = col & 31;
        if (mode == 1) {
            g_Q[(((size_t)(b * NHEAD + h) * L_SEQ) + l) * HDIM + d] = val * SCALE;
        } else if (mode == 2) {
            g_K[(((size_t)(b * NHEAD + h) * L_SEQ) + l) * HDIM + kperm32(d)] =
                __uint_as_float(f2tf(val));
        } else {
            g_V[((size_t)(b * NHEAD + h) * HDIM + d) * L_SEQ + vperm(l)] =
                __uint_as_float(f2tf(val));
        }
    }
}

// ---------------------------------------------------------------------------
// Projection core (pre-split operands): out[TM x 64] tile per CTA, K in 8
// chunks of 32, double-buffered cp.async. TM=128 -> 256 thr, TM=64 -> 128.
// ---------------------------------------------------------------------------
template<int TM>
__device__ __forceinline__ void proj_core(const float* __restrict__ Agh,
                                          const float* __restrict__ Agl,
                                          const float* __restrict__ Wgh,
                                          const float* __restrict__ Wgl,
                                          const float* __restrict__ bias,
                                          float* __restrict__ out, int mode)
{
    constexpr int NTHR = TM * 2;
    constexpr int PB = (TM + 64) * 72;            // floats per buffer

    extern __shared__ float sm[];
    const int tid = threadIdx.x;
    const int warp = tid >> 5, lane = tid & 31;
    const int g = lane >> 2, q = lane & 3;
    const int bm = blockIdx.y * TM, bn = blockIdx.x * 64;

    const uint32_t smb = (uint32_t)__cvta_generic_to_shared(sm);

    auto issue = [&](int t, int buf) {
        uint32_t base = smb + (uint32_t)buf * PB * 4;
        uint32_t aAh = base;
        uint32_t aAl = base + TM * 36 * 4;
        uint32_t aWh = base + TM * 72 * 4;
        uint32_t aWl = aWh + 64 * 36 * 4;
        #pragma unroll
        for (int j = 0; j < 4; j++) {
            int i = tid + NTHR * j;
            int row = i >> 3, c = (i & 7) * 4;
            size_t go = (size_t)(bm + row) * EMB + t * 32 + c;
            CP_ASYNC16(aAh + (row * 36 + c) * 4, Agh + go);
            CP_ASYNC16(aAl + (row * 36 + c) * 4, Agl + go);
        }
        #pragma unroll
        for (int j = 0; j < 512 / NTHR; j++) {
            int i = tid + NTHR * j;
            int row = i >> 3, c = (i & 7) * 4;
            size_t go = (size_t)(bn + row) * EMB + t * 32 + c;
            CP_ASYNC16(aWh + (row * 36 + c) * 4, Wgh + go);
            CP_ASYNC16(aWl + (row * 36 + c) * 4, Wgl + go);
        }
        CP_COMMIT();
    };

    float acc[8][4] = {};
    issue(0, 0);

    for (int t = 0; t < 8; t++) {
        CP_WAIT0();
        __syncthreads();
        if (t + 1 < 8) issue(t + 1, (t + 1) & 1);

        const float* base = sm + (t & 1) * PB;
        const float* sAh = base;
        const float* sAl = base + TM * 36;
        const float* sWh = base + TM * 72;
        const float* sWl = base + TM * 72 + 64 * 36;

        int ra0 = (warp * 16 + g) * 36 + q * 8;
        int ra1 = ra0 + 8 * 36;
        float4 h00 = *(const float4*)&sAh[ra0], h01 = *(const float4*)&sAh[ra0 + 4];
        float4 h10 = *(const float4*)&sAh[ra1], h11 = *(const float4*)&sAh[ra1 + 4];
        float4 l00 = *(const float4*)&sAl[ra0], l01 = *(const float4*)&sAl[ra0 + 4];
        float4 l10 = *(const float4*)&sAl[ra1], l11 = *(const float4*)&sAl[ra1 + 4];
        float ah0[8] = {h00.x, h00.y, h00.z, h00.w, h01.x, h01.y, h01.z, h01.w};
        float ah1[8] = {h10.x, h10.y, h10.z, h10.w, h11.x, h11.y, h11.z, h11.w};
        float al0[8] = {l00.x, l00.y, l00.z, l00.w, l01.x, l01.y, l01.z, l01.w};
        float al1[8] = {l10.x, l10.y, l10.z, l10.w, l11.x, l11.y, l11.z, l11.w};

        #pragma unroll
        for (int nt = 0; nt < 8; nt++) {
            int rw = (nt * 8 + g) * 36 + q * 8;
            float4 w0 = *(const float4*)&sWh[rw], w1 = *(const float4*)&sWh[rw + 4];
            float4 x0 = *(const float4*)&sWl[rw], x1 = *(const float4*)&sWl[rw + 4];
            float wh[8] = {w0.x, w0.y, w0.z, w0.w, w1.x, w1.y, w1.z, w1.w};
            float wl[8] = {x0.x, x0.y, x0.z, x0.w, x1.x, x1.y, x1.z, x1.w};
            #pragma unroll
            for (int kc = 0; kc < 4; kc++) {
                uint32_t A0 = fu(ah0[kc * 2]),     A1 = fu(ah1[kc * 2]);
                uint32_t A2 = fu(ah0[kc * 2 + 1]), A3 = fu(ah1[kc * 2 + 1]);
                uint32_t L0 = fu(al0[kc * 2]),     L1 = fu(al1[kc * 2]);
                uint32_t L2 = fu(al0[kc * 2 + 1]), L3 = fu(al1[kc * 2 + 1]);
                uint32_t B0 = fu(wh[kc * 2]), B1 = fu(wh[kc * 2 + 1]);
                uint32_t C0 = fu(wl[kc * 2]), C1 = fu(wl[kc * 2 + 1]);
                mma8(acc[nt], A0, A1, A2, A3, B0, B1);   // hi*hi
                mma8(acc[nt], L0, L1, L2, L3, B0, B1);   // lo*hi
                mma8(acc[nt], A0, A1, A2, A3, C0, C1);   // hi*lo
            }
        }
        __syncthreads();
    }

    const int r0 = bm + warp * 16 + g;
    #pragma unroll
    for (int nt = 0; nt < 8; nt++) {
        int col = bn + nt * 8 + 2 * q;
        store_proj(out, mode, r0,     col,     acc[nt][0] + bias[col]);
        store_proj(out, mode, r0,     col + 1, acc[nt][1] + bias[col + 1]);
        store_proj(out, mode, r0 + 8, col,     acc[nt][2] + bias[col]);
        store_proj(out, mode, r0 + 8, col + 1, acc[nt][3] + bias[col + 1]);
    }
}

__global__ __launch_bounds__(256)
void qkv_proj_v3(const float* __restrict__ bq, const float* __restrict__ bk,
                 const float* __restrict__ bv)
{
    int z = blockIdx.z;
    const float* bias = (z == 0) ? bq : (z == 1) ? bk : bv;
    proj_core<128>(gAh[z], gAl[z], gWh[z], gWl[z], bias, nullptr, z + 1);
}

__global__ __launch_bounds__(128)
void final_proj_v3(const float* __restrict__ bp, float* __restrict__ out)
{
    proj_core<64>(gOh, gOl, gWh[3], gWl[3], bp, out, 0);
}

// ---------------------------------------------------------------------------
// Flash attention (same core as R2). Epilogue writes hi/lo permuted gO.
// ---------------------------------------------------------------------------
__global__ __launch_bounds__(128)
void attn_mma()
{
    __shared__ float Ks[2][64 * KS_STRIDE];
    __shared__ float VT[2][32 * VT_STRIDE];

    const int bh = blockIdx.y;
    const int tid = threadIdx.x;
    const int warp = tid >> 5, lane = tid & 31;
    const int g = lane >> 2, q = lane & 3;
    const int qbase = blockIdx.x * 64;

    const float* Qb = g_Q + (size_t)bh * L_SEQ * HDIM;
    const float* Kb = g_K + (size_t)bh * L_SEQ * HDIM;
    const float* Vb = g_V + (size_t)bh * HDIM * L_SEQ;

    uint32_t ks_s[2], vt_s[2];
    ks_s[0] = (uint32_t)__cvta_generic_to_shared(&Ks[0][0]);
    ks_s[1] = (uint32_t)__cvta_generic_to_shared(&Ks[1][0]);
    vt_s[0] = (uint32_t)__cvta_generic_to_shared(&VT[0][0]);
    vt_s[1] = (uint32_t)__cvta_generic_to_shared(&VT[1][0]);

    auto issue_tile = [&](int t, int buf) {
        const float* Kt = Kb + (size_t)t * 64 * HDIM;
        const float* Vt = Vb + (size_t)t * 64;
        #pragma unroll
        for (int j = 0; j < 4; j++) {
            int i = tid + 128 * j;
            int row = i >> 3, c = (i & 7) * 4;
            CP_ASYNC16(ks_s[buf] + (row * KS_STRIDE + c) * 4, Kt + row * HDIM + c);
        }
        #pragma unroll
        for (int j = 0; j < 4; j++) {
            int i = tid + 128 * j;
            int row = i >> 4, c = (i & 15) * 4;
            int cc = c + ((c >= 32) ? 4 : 0);
            CP_ASYNC16(vt_s[buf] + (row * VT_STRIDE + cc) * 4, Vt + (size_t)row * L_SEQ + c);
        }
        CP_COMMIT();
    };

    issue_tile(0, 0);

    const int r0 = qbase + warp * 16 + g;

    uint32_t aq[4][4];
    #pragma unroll
    for (int kc = 0; kc < 4; kc++) {
        aq[kc][0] = f2tf(Qb[(size_t)r0 * HDIM + kc * 8 + q]);
        aq[kc][1] = f2tf(Qb[(size_t)(r0 + 8) * HDIM + kc * 8 + q]);
        aq[kc][2] = f2tf(Qb[(size_t)r0 * HDIM + kc * 8 + q + 4]);
        aq[kc][3] = f2tf(Qb[(size_t)(r0 + 8) * HDIM + kc * 8 + q + 4]);
    }

    float o[4][4] = {};
    float m0 = -1e30f, m1 = -1e30f, l0 = 0.f, l1 = 0.f;

    const int vt_q_base = q * 16 + ((q >= 2) ? 4 : 0);

    for (int t = 0; t < L_SEQ / 64; t++) {
        CP_WAIT0();
        __syncthreads();
        if (t + 1 < L_SEQ / 64) issue_tile(t + 1, (t + 1) & 1);
        const int buf = t & 1;

        float s[8][4] = {};
        #pragma unroll
        for (int nt = 0; nt < 8; nt++) {
            const float* kr = &Ks[buf][(nt * 8 + g) * KS_STRIDE + q * 8];
            float4 b01 = *(const float4*)kr;
            float4 b23 = *(const float4*)(kr + 4);
            mma8(s[nt], aq[0][0], aq[0][1], aq[0][2], aq[0][3], fu(b01.x), fu(b01.y));
            mma8(s[nt], aq[1][0], aq[1][1], aq[1][2], aq[1][3], fu(b01.z), fu(b01.w));
            mma8(s[nt], aq[2][0], aq[2][1], aq[2][2], aq[2][3], fu(b23.x), fu(b23.y));
            mma8(s[nt], aq[3][0], aq[3][1], aq[3][2], aq[3][3], fu(b23.z), fu(b23.w));
        }

        float mx0 = -1e30f, mx1 = -1e30f;
        #pragma unroll
        for (int nt = 0; nt < 8; nt++) {
            mx0 = fmaxf(mx0, fmaxf(s[nt][0], s[nt][1]));
            mx1 = fmaxf(mx1, fmaxf(s[nt][2], s[nt][3]));
        }
        mx0 = fmaxf(mx0, __shfl_xor_sync(0xffffffffu, mx0, 1));
        mx0 = fmaxf(mx0, __shfl_xor_sync(0xffffffffu, mx0, 2));
        mx1 = fmaxf(mx1, __shfl_xor_sync(0xffffffffu, mx1, 1));
        mx1 = fmaxf(mx1, __shfl_xor_sync(0xffffffffu, mx1, 2));
        float nm0 = fmaxf(m0, mx0), nm1 = fmaxf(m1, mx1);
        float cr0 = __expf(m0 - nm0), cr1 = __expf(m1 - nm1);
        m0 = nm0; m1 = nm1;

        float sum0 = 0.f, sum1 = 0.f;
        #pragma unroll
        for (int nt = 0; nt < 8; nt++) {
            s[nt][0] = __expf(s[nt][0] - nm0);
            s[nt][1] = __expf(s[nt][1] - nm0);
            s[nt][2] = __expf(s[nt][2] - nm1);
            s[nt][3] = __expf(s[nt][3] - nm1);
            sum0 += s[nt][0] + s[nt][1];
            sum1 += s[nt][2] + s[nt][3];
        }
        sum0 += __shfl_xor_sync(0xffffffffu, sum0, 1);
        sum0 += __shfl_xor_sync(0xffffffffu, sum0, 2);
        sum1 += __shfl_xor_sync(0xffffffffu, sum1, 1);
        sum1 += __shfl_xor_sync(0xffffffffu, sum1, 2);
        l0 = l0 * cr0 + sum0;
        l1 = l1 * cr1 + sum1;

        #pragma unroll
        for (int vt = 0; vt < 4; vt++) {
            o[vt][0] *= cr0; o[vt][1] *= cr0;
            o[vt][2] *= cr1; o[vt][3] *= cr1;
        }

        uint32_t pa[8][4];
        #pragma unroll
        for (int kc = 0; kc < 8; kc++) {
            pa[kc][0] = f2tf(s[kc][0]);
            pa[kc][1] = f2tf(s[kc][2]);
            pa[kc][2] = f2tf(s[kc][1]);
            pa[kc][3] = f2tf(s[kc][3]);
        }

        #pragma unroll
        for (int vt = 0; vt < 4; vt++) {
            const float* vr = &VT[buf][(vt * 8 + g) * VT_STRIDE + vt_q_base];
            float4 v0 = *(const float4*)vr;
            float4 v1 = *(const float4*)(vr + 4);
            float4 v2 = *(const float4*)(vr + 8);
            float4 v3 = *(const float4*)(vr + 12);
            mma8(o[vt], pa[0][0], pa[0][1], pa[0][2], pa[0][3], fu(v0.x), fu(v0.y));
            mma8(o[vt], pa[1][0], pa[1][1], pa[1][2], pa[1][3], fu(v0.z), fu(v0.w));
            mma8(o[vt], pa[2][0], pa[2][1], pa[2][2], pa[2][3], fu(v1.x), fu(v1.y));
            mma8(o[vt], pa[3][0], pa[3][1], pa[3][2], pa[3][3], fu(v1.z), fu(v1.w));
            mma8(o[vt], pa[4][0], pa[4][1], pa[4][2], pa[4][3], fu(v2.x), fu(v2.y));
            mma8(o[vt], pa[5][0], pa[5][1], pa[5][2], pa[5][3], fu(v2.z), fu(v2.w));
            mma8(o[vt], pa[6][0], pa[6][1], pa[6][2], pa[6][3], fu(v3.x), fu(v3.y));
            mma8(o[vt], pa[7][0], pa[7][1], pa[7][2], pa[7][3], fu(v3.z), fu(v3.w));
        }
    }

    // epilogue: write hi/lo permuted directly for the final projection
    const int b = bh >> 3, h = bh & 7;
    float iv0 = 1.f / l0, iv1 = 1.f / l1;
    #pragma unroll
    for (int vt = 0; vt < 4; vt++) {
        #pragma unroll
        for (int e = 0; e < 2; e++) {
            int cc = vt * 8 + 2 * q + e;
            int idx = h * 32 + kperm32(cc);
            float v0 = o[vt][e] * iv0;
            float v1 = o[vt][2 + e] * iv1;
            uint32_t h0 = f2tf(v0), h1 = f2tf(v1);
            size_t row0 = (size_t)(r0 * BATCH + b) * EMB;
            size_t row1 = (size_t)((r0 + 8) * BATCH + b) * EMB;
            gOh[row0 + idx] = __uint_as_float(h0);
            gOl[row0 + idx] = __uint_as_float(f2tf(v0 - __uint_as_float(h0)));
            gOh[row1 + idx] = __uint_as_float(h1);
            gOl[row1 + idx] = __uint_as_float(f2tf(v1 - __uint_as_float(h1)));
        }
    }
}

// ---------------------------------------------------------------------------
extern "C" void kernel_launch(void* const* d_in, const int* in_sizes, int n_in,
                              void* d_out, int out_size)
{
    const float* query = (const float*)d_in[0];
    const float* key_  = (const float*)d_in[1];
    const float* value = (const float*)d_in[2];
    const float* bq    = (const float*)d_in[4];
    const float* bk    = (const float*)d_in[6];
    const float* bv    = (const float*)d_in[8];
    const float* bp    = (const float*)d_in[10];
    const float* Wq    = (const float*)d_in[3];
    const float* Wk    = (const float*)d_in[5];
    const float* Wv    = (const float*)d_in[7];
    const float* Wp    = (const float*)d_in[9];
    float* out = (float*)d_out;

    const int SMEM_QKV = (128 + 64) * 72 * 2 * 4;   // 110592 B
    const int SMEM_FIN = (64 + 64) * 72 * 2 * 4;    //  73728 B
    static bool attr_done = false;
    if (!attr_done) {
        cudaFuncSetAttribute(qkv_proj_v3,
                             cudaFuncAttributeMaxDynamicSharedMemorySize, SMEM_QKV);
        cudaFuncSetAttribute(final_proj_v3,
                             cudaFuncAttributeMaxDynamicSharedMemorySize, SMEM_FIN);
        attr_done = true;
    }

    split_act<<<3072, 256>>>(query, key_, value);
    split_w<<<256, 256>>>(Wq, Wk, Wv, Wp);

    qkv_proj_v3<<<dim3(EMB / 64, MROWS / 128, 3), 256, SMEM_QKV>>>(bq, bk, bv);

    attn_mma<<<dim3(L_SEQ / 64, BATCH * NHEAD), 128>>>();

    final_proj_v3<<<dim3(EMB / 64, MROWS / 64), 128, SMEM_FIN>>>(bp, out);
}